// round 9
// baseline (speedup 1.0000x reference)
#include <cuda_runtime.h>
#include <stdint.h>

// Problem constants
#define BINSD   512
#define BATCH   64
#define NPTS    4096
#define CELLS   (BATCH * BINSD * BINSD)      // 16,777,216 cells
#define NPOINTS (BATCH * NPTS)               // 262,144 points

// Fused grid: 1024 scatter blocks interleaved every 65th bid among 65536 fill
// blocks -> scatter is ~1.5% of resident blocks at any instant (hidden under
// the DRAM-bound fill) instead of monopolizing wave 0.
#define INTERLEAVE  65
#define TOTAL_BLOCKS (INTERLEAVE * 1024)     // 66560 = 1024 scatter + 65536 fill

// Per-cell winner token: 0 = empty, else (n+1) of the winning point in-batch.
// Zero at module load; resolve's atomicExch self-cleans every touched cell,
// so each graph replay starts from identical state.
static __device__ unsigned int g_winner[CELLS];

// ---------------------------------------------------------------------------
// Kernel 1 (fused): every 65th block scatters 256 points (returnless
// atomicMax); all other blocks do the R1-shaped fill — ONE float4 store per
// thread (the only store shape measured at 67% DRAM; batched loops gave 45%).
// ---------------------------------------------------------------------------
__global__ void __launch_bounds__(256) fused_scatter_fill_kernel(
    float4* __restrict__ out, const float2* __restrict__ pts) {
    unsigned bid = blockIdx.x;
    unsigned q = bid / INTERLEAVE;                 // scatter-block ordinal
    if (bid == q * INTERLEAVE) {
        // ---- scatter: one point per thread ----
        int t = q * 256 + threadIdx.x;             // 0 .. NPOINTS-1
        float2 p = pts[t];
        // delta = 1/512 exactly: x/delta == x*512.0f bit-exactly; truncation
        // matches astype(int32) for non-negative inputs.
        int row = (int)(p.x * 512.0f);
        int col = (int)(p.y * 512.0f);
        int cell = ((t >> 12) << 18) | (row << 9) | col;
        unsigned int tok = (unsigned int)(t & (NPTS - 1)) + 1u;
        atomicMax(&g_winner[cell], tok);           // no return -> RED path
    } else {
        // ---- fill: one float4 per thread ----
        int idx = (int)(bid - q - 1) * 256 + threadIdx.x;   // 0 .. CELLS-1
        const float inv = 1.0f / (float)BINSD;
        int j = idx & (BINSD - 1);
        int i = (idx >> 9) & (BINSD - 1);
        out[idx] = make_float4(0.63f, 0.63f, (float)j * inv, (float)i * inv);
    }
}

// ---------------------------------------------------------------------------
// Kernel 2: resolve via atomicExch. Each thread exchanges 0 into its point's
// cell: exactly one thread per cell receives the nonzero winner token (and
// the cell is simultaneously reset for the next replay — one random RMW
// instead of load + separate reset store). That thread writes the winning
// point: its own if the token matches (~99.99% of cases), else one hot-L2
// reload of pts[winner].
// ---------------------------------------------------------------------------
__global__ void __launch_bounds__(256) resolve_kernel(
    float4* __restrict__ out, const float2* __restrict__ pts) {
    int t = blockIdx.x * 256 + threadIdx.x;        // 0 .. NPOINTS-1
    float2 p = pts[t];
    int b = t >> 12;
    int row = (int)(p.x * 512.0f);
    int col = (int)(p.y * 512.0f);
    int cell = (b << 18) | (row << 9) | col;
    unsigned int mytok = (unsigned int)(t & (NPTS - 1)) + 1u;

    unsigned int wtok = atomicExch(&g_winner[cell], 0u);
    if (wtok != 0u) {
        float2 wp = p;
        if (wtok != mytok)                          // rare collision loser got it
            wp = pts[(b << 12) | (int)(wtok - 1u)];
        out[cell] = make_float4(1.0f, 1.0f, wp.x, wp.y);
    }
}

extern "C" void kernel_launch(void* const* d_in, const int* in_sizes, int n_in,
                              void* d_out, int out_size) {
    const float2* pts = (const float2*)d_in[0];   // batch [64, 4096, 2] fp32
    float4* out = (float4*)d_out;                 // [64, 512, 512, 4] fp32

    fused_scatter_fill_kernel<<<TOTAL_BLOCKS, 256>>>(out, pts);
    resolve_kernel<<<NPOINTS / 256, 256>>>(out, pts);
}

// round 10
// speedup vs baseline: 1.0909x; 1.0909x over previous
#include <cuda_runtime.h>
#include <stdint.h>

// Problem constants
#define BINSD   512
#define BATCH   64
#define NPTS    4096
#define CELLS   (BATCH * BINSD * BINSD)      // 16,777,216 cells
#define NPOINTS (BATCH * NPTS)               // 262,144 points

#define FILL_BLOCKS 65536                    // 65536*256 = CELLS, 1 store/thread
#define SCAT_BLOCKS 1024                     // 1024*256 = NPOINTS, 1 pt/thread

// Per-cell winner token: 0 = empty, else (n+1) of the winning point in-batch.
// Zero at module load; resolve's atomicExch self-cleans every touched cell,
// so each graph replay starts from identical state.
static __device__ unsigned int g_winner[CELLS];

// ---------------------------------------------------------------------------
// Kernel 1 (fused): fill blocks occupy bids [0, 65536) — dispatched first, in
// the R1-exact shape (ONE float4 store per thread; the only store shape
// measured at 67% DRAM — batched loops gave 45%, head/interleaved scatter
// placement gave 50+/55+ us). Scatter blocks sit at the TAIL of the grid
// (bids >= 65536): they run in the final wave, overlapping their atomic
// latency with the drain of the last fill stores instead of competing with
// peak store issue.
// ---------------------------------------------------------------------------
__global__ void __launch_bounds__(256) fused_fill_scatter_kernel(
    float4* __restrict__ out, const float2* __restrict__ pts) {
    unsigned bid = blockIdx.x;

    if (bid < FILL_BLOCKS) {
        // ---- fill: one float4 per thread ----
        int idx = bid * 256 + threadIdx.x;               // 0 .. CELLS-1
        const float inv = 1.0f / (float)BINSD;
        int j = idx & (BINSD - 1);
        int i = (idx >> 9) & (BINSD - 1);
        out[idx] = make_float4(0.63f, 0.63f, (float)j * inv, (float)i * inv);
    } else {
        // ---- scatter: one point per thread, returnless atomic (RED) ----
        int t = (int)(bid - FILL_BLOCKS) * 256 + threadIdx.x;  // 0 .. NPOINTS-1
        float2 p = pts[t];
        // delta = 1/512 exactly: x/delta == x*512.0f bit-exactly; truncation
        // matches astype(int32) for non-negative inputs.
        int row = (int)(p.x * 512.0f);
        int col = (int)(p.y * 512.0f);
        int cell = ((t >> 12) << 18) | (row << 9) | col;
        unsigned int tok = (unsigned int)(t & (NPTS - 1)) + 1u;
        atomicMax(&g_winner[cell], tok);                 // no return -> RED
    }
}

// ---------------------------------------------------------------------------
// Kernel 2: resolve via atomicExch. Each thread exchanges 0 into its point's
// cell: exactly one thread per cell receives the nonzero winner token (cell
// simultaneously reset for the next replay — one random RMW instead of
// load + separate reset store). That thread writes the winning point: its
// own if the token matches (~99.99% of threads), else one hot-L2 reload.
// ---------------------------------------------------------------------------
__global__ void __launch_bounds__(256) resolve_kernel(
    float4* __restrict__ out, const float2* __restrict__ pts) {
    int t = blockIdx.x * 256 + threadIdx.x;              // 0 .. NPOINTS-1
    float2 p = pts[t];
    int b = t >> 12;
    int row = (int)(p.x * 512.0f);
    int col = (int)(p.y * 512.0f);
    int cell = (b << 18) | (row << 9) | col;
    unsigned int mytok = (unsigned int)(t & (NPTS - 1)) + 1u;

    unsigned int wtok = atomicExch(&g_winner[cell], 0u);
    if (wtok != 0u) {
        float2 wp = p;
        if (wtok != mytok)                               // rare collision loser
            wp = pts[(b << 12) | (int)(wtok - 1u)];
        out[cell] = make_float4(1.0f, 1.0f, wp.x, wp.y);
    }
}

extern "C" void kernel_launch(void* const* d_in, const int* in_sizes, int n_in,
                              void* d_out, int out_size) {
    const float2* pts = (const float2*)d_in[0];   // batch [64, 4096, 2] fp32
    float4* out = (float4*)d_out;                 // [64, 512, 512, 4] fp32

    fused_fill_scatter_kernel<<<FILL_BLOCKS + SCAT_BLOCKS, 256>>>(out, pts);
    resolve_kernel<<<NPOINTS / 256, 256>>>(out, pts);
}

// round 11
// speedup vs baseline: 1.1245x; 1.0307x over previous
#include <cuda_runtime.h>
#include <stdint.h>

// Problem constants
#define BINSD   512
#define BATCH   64
#define NPTS    4096
#define CELLS   (BATCH * BINSD * BINSD)      // 16,777,216 cells
#define FILL_BLOCKS 65536                    // 65536*256 = CELLS, 1 store/thread

// smem hash: 8192 slots, one uint32 each = 32 KB.
// entry = (cell18 << 13) | tok13, tok in 1..4096 (so occupied entries != 0).
#define HASH_SLOTS 8192
#define HASH_MASK  (HASH_SLOTS - 1)

// ---------------------------------------------------------------------------
// Kernel 1: background fill — R1-exact shape (ONE float4 store per thread,
// huge grid; the only store shape measured at 67% DRAM on this chip).
// ---------------------------------------------------------------------------
__global__ void __launch_bounds__(256) fill_kernel(float4* __restrict__ out) {
    int idx = blockIdx.x * 256 + threadIdx.x;          // 0 .. CELLS-1
    const float inv = 1.0f / (float)BINSD;
    int j = idx & (BINSD - 1);
    int i = (idx >> 9) & (BINSD - 1);
    out[idx] = make_float4(0.63f, 0.63f, (float)j * inv, (float)i * inv);
}

// ---------------------------------------------------------------------------
// Kernel 2: one block per batch. Dedup the batch's 4096 points in a shared
// memory hash (last-write-wins == max token, exact), then write winner cells
// straight into out. No persistent global state, no global atomics.
// ---------------------------------------------------------------------------
__global__ void __launch_bounds__(1024) scatter_resolve_kernel(
    float4* __restrict__ out, const float4* __restrict__ pts4) {
    __shared__ unsigned int h[HASH_SLOTS];

    int b   = blockIdx.x;                              // batch id
    int tid = threadIdx.x;

    // init hash (8 slots/thread)
    #pragma unroll
    for (int s = 0; s < 8; s++) h[tid + s * 1024] = 0u;
    __syncthreads();

    // ---- insert: 4 points per thread (two coalesced float4 loads) ----
    int t0 = tid * 4;                                  // point index in batch
    const float4* base4 = pts4 + ((size_t)b << 11);    // b*4096 pts = b*2048 f4
    float4 A = base4[tid * 2];
    float4 B = base4[tid * 2 + 1];
    float px[4] = {A.x, A.z, B.x, B.z};
    float py[4] = {A.y, A.w, B.y, B.w};

    #pragma unroll
    for (int k = 0; k < 4; k++) {
        // delta = 1/512 exactly: x/delta == x*512.0f bit-exactly; truncation
        // matches astype(int32) for non-negative inputs.
        int row = (int)(px[k] * 512.0f);
        int col = (int)(py[k] * 512.0f);
        unsigned int cell = (unsigned int)((row << 9) | col);     // 18 bits
        unsigned int tok  = (unsigned int)(t0 + k) + 1u;          // 1..4096
        unsigned int ent  = (cell << 13) | tok;
        unsigned int slot = cell & HASH_MASK;

        // open addressing: claim empty slot via CAS, or atomicMax on own key
        // (same key bits -> max picks max token = last write in ref order).
        for (;;) {
            unsigned int cur = h[slot];
            if (cur == 0u) {
                unsigned int prev = atomicCAS(&h[slot], 0u, ent);
                if (prev == 0u) break;
                cur = prev;
            }
            if ((cur >> 13) == cell) { atomicMax(&h[slot], ent); break; }
            slot = (slot + 1) & HASH_MASK;
        }
    }
    __syncthreads();

    // ---- readout: 8 slots/thread; winners write their cells ----
    const float2* base2 = (const float2*)base4;        // pts of this batch
    size_t outbase = (size_t)b << 18;
    #pragma unroll
    for (int s = 0; s < 8; s++) {
        unsigned int ent = h[tid + s * 1024];
        if (ent != 0u) {
            unsigned int cell = ent >> 13;
            unsigned int tok  = ent & 0x1FFFu;         // 13 bits
            float2 wp = base2[tok - 1u];               // L2-hot reload
            out[outbase + cell] = make_float4(1.0f, 1.0f, wp.x, wp.y);
        }
    }
}

extern "C" void kernel_launch(void* const* d_in, const int* in_sizes, int n_in,
                              void* d_out, int out_size) {
    const float4* pts4 = (const float4*)d_in[0];  // batch [64, 4096, 2] fp32
    float4* out = (float4*)d_out;                 // [64, 512, 512, 4] fp32

    fill_kernel<<<FILL_BLOCKS, 256>>>(out);
    scatter_resolve_kernel<<<BATCH, 1024>>>(out, pts4);
}